// round 1
// baseline (speedup 1.0000x reference)
#include <cuda_runtime.h>
#include <cuda_bf16.h>
#include <math.h>

// Problem constants
#define Bv 8
#define Sv 1024
#define Dv 512
#define Hv 8
#define DHv 1024          // per-head dim = 2*D
#define HDH 8192          // H*DH
#define Mrows 8192        // B*S

// -------------------- scratch (device globals; no allocation) --------------------
__device__ float g_q  [67108864];   // [B*S, H*DH]
__device__ float g_k  [67108864];
__device__ float g_v  [67108864];
__device__ float g_sc [67108864];   // [B*H, S, S] scores -> attn
__device__ float g_ctx[67108864];   // [B*S, H*DH]
__device__ float g_res[ 4194304];   // [B*S, D] pre-LayerNorm
__device__ int   g_mask_mode;       // 0 = f32, 1 = i32, 2 = u8

// -------------------- mask dtype sniffer --------------------
__global__ void detect_mask_kernel(const void* __restrict__ mask) {
    __shared__ int sF, sI;
    if (threadIdx.x == 0) { sF = 1; sI = 1; }
    __syncthreads();
    const float* mf = (const float*)mask;
    const int*   mi = (const int*)mask;
    int okF = 1, okI = 1;
    for (int i = threadIdx.x; i < 16384; i += 256) {
        float f = mf[i];
        okF &= ((f == 0.0f) | (f == 1.0f));
        int v = mi[i];
        okI &= ((v == 0) | (v == 1));
    }
    atomicAnd(&sF, okF);
    atomicAnd(&sI, okI);
    __syncthreads();
    if (threadIdx.x == 0) g_mask_mode = sF ? 0 : (sI ? 1 : 2);
}

// -------------------- generic 128x128x8 fp32 GEMM --------------------
// C[m,n] = sum_k A[m,k] * (TRANSB ? B[n,k] : B[k,n])  (+ bias[n]) (+ resid[m,n])
// blockIdx.z selects a (batch, head) slice via linear offsets.
template<bool TRANSB>
__global__ void __launch_bounds__(256, 2) sgemm_kernel(
    const float* __restrict__ A, const float* __restrict__ B,
    float* __restrict__ C,
    const float* __restrict__ bias, const float* __restrict__ resid,
    int K, int lda, int ldb, int ldc,
    long aOffB, long aOffH, long bOffB, long bOffH,
    long cOffB, long cOffH, int Hdim)
{
    __shared__ float As[8][132];
    __shared__ float Bs[8][132];

    const int z  = blockIdx.z;
    const int zb = z / Hdim, zh = z % Hdim;
    A += (long)zb * aOffB + (long)zh * aOffH;
    B += (long)zb * bOffB + (long)zh * bOffH;
    const long coff = (long)zb * cOffB + (long)zh * cOffH;
    C += coff;
    if (resid) resid += coff;

    const int m0 = blockIdx.y * 128;
    const int n0 = blockIdx.x * 128;
    const int t  = threadIdx.x;
    const int tx = t & 15, ty = t >> 4;

    float acc[8][8];
#pragma unroll
    for (int i = 0; i < 8; i++)
#pragma unroll
        for (int j = 0; j < 8; j++) acc[i][j] = 0.0f;

    const int arow = t >> 1;            // 0..127
    const int ak4  = (t & 1) << 2;      // 0 or 4
    const int brow = t >> 5;            // 0..7
    const int bn4  = (t & 31) << 2;     // 0..124

    const float* Aptr = A + (long)(m0 + arow) * lda + ak4;
    const float* Bptr;
    if (TRANSB) Bptr = B + (long)(n0 + arow) * ldb + ak4;
    else        Bptr = B + (long)brow * ldb + n0 + bn4;

    for (int kt = 0; kt < K; kt += 8) {
        float4 av = *reinterpret_cast<const float4*>(Aptr + kt);
        float4 bv;
        if (TRANSB) bv = *reinterpret_cast<const float4*>(Bptr + kt);
        else        bv = *reinterpret_cast<const float4*>(Bptr + (long)kt * ldb);

        __syncthreads();
        As[ak4 + 0][arow] = av.x;
        As[ak4 + 1][arow] = av.y;
        As[ak4 + 2][arow] = av.z;
        As[ak4 + 3][arow] = av.w;
        if (TRANSB) {
            Bs[ak4 + 0][arow] = bv.x;
            Bs[ak4 + 1][arow] = bv.y;
            Bs[ak4 + 2][arow] = bv.z;
            Bs[ak4 + 3][arow] = bv.w;
        } else {
            *reinterpret_cast<float4*>(&Bs[brow][bn4]) = bv;
        }
        __syncthreads();

#pragma unroll
        for (int k = 0; k < 8; k++) {
            float4 a0 = *reinterpret_cast<const float4*>(&As[k][ty * 8]);
            float4 a1 = *reinterpret_cast<const float4*>(&As[k][ty * 8 + 4]);
            float4 b0 = *reinterpret_cast<const float4*>(&Bs[k][tx * 8]);
            float4 b1 = *reinterpret_cast<const float4*>(&Bs[k][tx * 8 + 4]);
            float ar[8] = {a0.x, a0.y, a0.z, a0.w, a1.x, a1.y, a1.z, a1.w};
            float br[8] = {b0.x, b0.y, b0.z, b0.w, b1.x, b1.y, b1.z, b1.w};
#pragma unroll
            for (int i = 0; i < 8; i++)
#pragma unroll
                for (int j = 0; j < 8; j++) acc[i][j] = fmaf(ar[i], br[j], acc[i][j]);
        }
    }

    // epilogue
#pragma unroll
    for (int i = 0; i < 8; i++) {
        const int m = m0 + ty * 8 + i;
        float* crow = C + (long)m * ldc + n0 + tx * 8;
        const float* rrow = resid ? (resid + (long)m * ldc + n0 + tx * 8) : nullptr;
#pragma unroll
        for (int j4 = 0; j4 < 8; j4 += 4) {
            float4 o;
            float vals[4];
#pragma unroll
            for (int u = 0; u < 4; u++) {
                float v = acc[i][j4 + u];
                if (bias) v += bias[n0 + tx * 8 + j4 + u];
                if (rrow) v += rrow[j4 + u];
                vals[u] = v;
            }
            o.x = vals[0]; o.y = vals[1]; o.z = vals[2]; o.w = vals[3];
            *reinterpret_cast<float4*>(crow + j4) = o;
        }
    }
}

// -------------------- masked scaled softmax over last dim (S=1024) --------------------
// One block per (b,h,i) row; applies scale 1/sqrt(DH) and mask -> -1e9, then softmax.
__global__ void __launch_bounds__(256) softmax_kernel(float* __restrict__ sc,
                                                      const void* __restrict__ mask)
{
    const long r = blockIdx.x;                // 0 .. B*H*S-1
    const int  i = (int)(r % Sv);
    const int  z = (int)(r / Sv);
    const int  b = z / Hv;
    float* row = sc + r * (long)Sv;
    const long mbase = ((long)b * Sv + i) * (long)Sv;
    const int mode = g_mask_mode;
    const int t = threadIdx.x;

    float v[4];
#pragma unroll
    for (int u = 0; u < 4; u++) {
        const int j = u * 256 + t;
        float s = row[j] * 0.03125f;          // 1/sqrt(1024)
        bool m;
        if (mode == 0)      m = ((const float*)mask)[mbase + j] != 0.0f;
        else if (mode == 1) m = ((const int*)mask)[mbase + j] != 0;
        else                m = ((const unsigned char*)mask)[mbase + j] != 0;
        v[u] = m ? -1e9f : s;
    }

    __shared__ float red[8];
    const int lane = t & 31, warp = t >> 5;

    // max reduction
    float mx = fmaxf(fmaxf(v[0], v[1]), fmaxf(v[2], v[3]));
#pragma unroll
    for (int o = 16; o > 0; o >>= 1) mx = fmaxf(mx, __shfl_xor_sync(0xffffffffu, mx, o));
    if (lane == 0) red[warp] = mx;
    __syncthreads();
    if (t < 32) {
        float m2 = (lane < 8) ? red[lane] : -3.4e38f;
#pragma unroll
        for (int o = 4; o > 0; o >>= 1) m2 = fmaxf(m2, __shfl_xor_sync(0xffffffffu, m2, o));
        if (lane == 0) red[0] = m2;
    }
    __syncthreads();
    mx = red[0];
    __syncthreads();

    // exp + sum reduction
    float sum = 0.0f;
#pragma unroll
    for (int u = 0; u < 4; u++) { v[u] = expf(v[u] - mx); sum += v[u]; }
#pragma unroll
    for (int o = 16; o > 0; o >>= 1) sum += __shfl_xor_sync(0xffffffffu, sum, o);
    if (lane == 0) red[warp] = sum;
    __syncthreads();
    if (t < 32) {
        float s2 = (lane < 8) ? red[lane] : 0.0f;
#pragma unroll
        for (int o = 4; o > 0; o >>= 1) s2 += __shfl_xor_sync(0xffffffffu, s2, o);
        if (lane == 0) red[0] = s2;
    }
    __syncthreads();
    const float inv = 1.0f / red[0];

#pragma unroll
    for (int u = 0; u < 4; u++) row[u * 256 + t] = v[u] * inv;
}

// -------------------- LayerNorm over D=512 --------------------
__global__ void __launch_bounds__(128) ln_kernel(const float* __restrict__ x,
                                                 const float* __restrict__ gamma,
                                                 const float* __restrict__ beta,
                                                 float* __restrict__ out)
{
    const int r = blockIdx.x;
    const float* xr = x + (long)r * Dv;
    const int t = threadIdx.x;
    const int lane = t & 31, warp = t >> 5;
    __shared__ float red[4];

    float v[4];
    float s = 0.0f;
#pragma unroll
    for (int u = 0; u < 4; u++) { v[u] = xr[u * 128 + t]; s += v[u]; }
#pragma unroll
    for (int o = 16; o > 0; o >>= 1) s += __shfl_xor_sync(0xffffffffu, s, o);
    if (lane == 0) red[warp] = s;
    __syncthreads();
    if (t < 32) {
        float s2 = (lane < 4) ? red[lane] : 0.0f;
#pragma unroll
        for (int o = 2; o > 0; o >>= 1) s2 += __shfl_xor_sync(0xffffffffu, s2, o);
        if (lane == 0) red[0] = s2;
    }
    __syncthreads();
    const float mu = red[0] * (1.0f / Dv);
    __syncthreads();

    float sq = 0.0f;
#pragma unroll
    for (int u = 0; u < 4; u++) { float d = v[u] - mu; sq += d * d; }
#pragma unroll
    for (int o = 16; o > 0; o >>= 1) sq += __shfl_xor_sync(0xffffffffu, sq, o);
    if (lane == 0) red[warp] = sq;
    __syncthreads();
    if (t < 32) {
        float s2 = (lane < 4) ? red[lane] : 0.0f;
#pragma unroll
        for (int o = 2; o > 0; o >>= 1) s2 += __shfl_xor_sync(0xffffffffu, s2, o);
        if (lane == 0) red[0] = s2;
    }
    __syncthreads();
    const float inv = rsqrtf(red[0] * (1.0f / Dv) + 1e-5f);

    float* orow = out + (long)r * Dv;
#pragma unroll
    for (int u = 0; u < 4; u++) {
        const int c = u * 128 + t;
        orow[c] = (v[u] - mu) * inv * gamma[c] + beta[c];
    }
}

// -------------------- launch --------------------
extern "C" void kernel_launch(void* const* d_in, const int* in_sizes, int n_in,
                              void* d_out, int out_size)
{
    const float* Q    = (const float*)d_in[0];
    const float* K    = (const float*)d_in[1];
    const float* V    = (const float*)d_in[2];
    const void*  mask = (const void*) d_in[3];
    const float* Wq   = (const float*)d_in[4];
    const float* bq   = (const float*)d_in[5];
    const float* Wk   = (const float*)d_in[6];
    const float* bk   = (const float*)d_in[7];
    const float* Wv   = (const float*)d_in[8];
    const float* bv   = (const float*)d_in[9];
    const float* Wo   = (const float*)d_in[10];
    const float* bo   = (const float*)d_in[11];
    const float* gamma= (const float*)d_in[12];
    const float* beta = (const float*)d_in[13];
    float* out = (float*)d_out;

    void *pq, *pk, *pv, *psc, *pctx, *pres;
    cudaGetSymbolAddress(&pq,  g_q);
    cudaGetSymbolAddress(&pk,  g_k);
    cudaGetSymbolAddress(&pv,  g_v);
    cudaGetSymbolAddress(&psc, g_sc);
    cudaGetSymbolAddress(&pctx,g_ctx);
    cudaGetSymbolAddress(&pres,g_res);
    float* fq  = (float*)pq;   float* fk  = (float*)pk;  float* fv = (float*)pv;
    float* fsc = (float*)psc;  float* fctx= (float*)pctx; float* fres = (float*)pres;

    detect_mask_kernel<<<1, 256>>>(mask);

    // QKV projections: [8192,512] x [512,8192]
    {
        dim3 grid(HDH / 128, Mrows / 128, 1);
        sgemm_kernel<false><<<grid, 256>>>(Q, Wq, fq, bq, nullptr,
            Dv, Dv, HDH, HDH, 0, 0, 0, 0, 0, 0, 1);
        sgemm_kernel<false><<<grid, 256>>>(K, Wk, fk, bk, nullptr,
            Dv, Dv, HDH, HDH, 0, 0, 0, 0, 0, 0, 1);
        sgemm_kernel<false><<<grid, 256>>>(V, Wv, fv, bv, nullptr,
            Dv, Dv, HDH, HDH, 0, 0, 0, 0, 0, 0, 1);
    }

    // scores: per (b,h): [S,DH] x [S,DH]^T -> [S,S]
    {
        dim3 grid(Sv / 128, Sv / 128, Bv * Hv);
        sgemm_kernel<true><<<grid, 256>>>(fq, fk, fsc, nullptr, nullptr,
            DHv, HDH, HDH, Sv,
            (long)Sv * HDH, (long)DHv,            // A offsets (b, h)
            (long)Sv * HDH, (long)DHv,            // B offsets
            (long)Hv * Sv * Sv, (long)Sv * Sv,    // C offsets
            Hv);
    }

    // masked softmax
    softmax_kernel<<<Bv * Hv * Sv, 256>>>(fsc, mask);

    // ctx: per (b,h): [S,S] x [S,DH] -> [S,DH]
    {
        dim3 grid(DHv / 128, Sv / 128, Bv * Hv);
        sgemm_kernel<false><<<grid, 256>>>(fsc, fv, fctx, nullptr, nullptr,
            Sv, Sv, HDH, HDH,
            (long)Hv * Sv * Sv, (long)Sv * Sv,    // A offsets
            (long)Sv * HDH, (long)DHv,            // B offsets
            (long)Sv * HDH, (long)DHv,            // C offsets
            Hv);
    }

    // output projection + bias + residual: [8192,8192] x [8192,512]
    {
        dim3 grid(Dv / 128, Mrows / 128, 1);
        sgemm_kernel<false><<<grid, 256>>>(fctx, Wo, fres, bo, Q,
            HDH, HDH, Dv, Dv, 0, 0, 0, 0, 0, 0, 1);
    }

    // LayerNorm
    ln_kernel<<<Mrows, 128>>>(fres, gamma, beta, out);
}

// round 3
// speedup vs baseline: 2.2781x; 2.2781x over previous
#include <cuda_runtime.h>
#include <cuda_bf16.h>
#include <cstdint>
#include <math.h>

// Problem constants
#define Bv 8
#define Sv 1024
#define Dv 512
#define Hv 8
#define DHv 1024          // per-head dim = 2*D
#define HDH 8192          // H*DH
#define Mrows 8192        // B*S

typedef __nv_bfloat16 bf16;

// -------------------- scratch (device globals; no allocation) --------------------
__device__ bf16 g_in_hi[12582912], g_in_lo[12582912];   // Q,K,V inputs split (3 x 4M)
__device__ bf16 g_w_hi [16777216], g_w_lo [16777216];   // Wq,Wk,Wv,Wo split (4 x 4M), natural layout
__device__ bf16 g_q_hi [67108864], g_q_lo [67108864];   // [B*S, H*DH]
__device__ bf16 g_k_hi [67108864], g_k_lo [67108864];
__device__ bf16 g_v_hi [67108864], g_v_lo [67108864];   // [B*S, H*DH]
__device__ bf16 g_at_hi[67108864], g_at_lo[67108864];   // attn [(b,h), i, j]
__device__ bf16 g_cx_hi[67108864], g_cx_lo[67108864];   // ctx [B*S, H*DH]
__device__ float g_sc [67108864];                       // scores fp32 [(b,h), i, j]
__device__ float g_res[ 4194304];                       // pre-LN fp32 [B*S, D]
__device__ int   g_mask_mode;

// -------------------- PTX helpers (baseline sm_80+ PTX only) --------------------
__device__ __forceinline__ uint32_t smem_u32(const void* p) {
    uint32_t a;
    asm("{ .reg .u64 t; cvta.to.shared.u64 t, %1; cvt.u32.u64 %0, t; }" : "=r"(a) : "l"(p));
    return a;
}
__device__ __forceinline__ void cpasync16(uint32_t s, const void* g) {
    asm volatile("cp.async.cg.shared.global [%0], [%1], 16;" :: "r"(s), "l"(g));
}
#define CP_COMMIT() asm volatile("cp.async.commit_group;")
#define CP_WAIT1()  asm volatile("cp.async.wait_group 1;")
#define CP_WAIT0()  asm volatile("cp.async.wait_group 0;")

__device__ __forceinline__ void ldsm4(uint32_t* r, uint32_t a) {
    asm volatile("ldmatrix.sync.aligned.m8n8.x4.shared.b16 {%0,%1,%2,%3}, [%4];"
                 : "=r"(r[0]), "=r"(r[1]), "=r"(r[2]), "=r"(r[3]) : "r"(a));
}
__device__ __forceinline__ void ldsm4t(uint32_t* r, uint32_t a) {
    asm volatile("ldmatrix.sync.aligned.m8n8.x4.trans.shared.b16 {%0,%1,%2,%3}, [%4];"
                 : "=r"(r[0]), "=r"(r[1]), "=r"(r[2]), "=r"(r[3]) : "r"(a));
}
__device__ __forceinline__ void mma16816(float* c, const uint32_t* a, const uint32_t* b) {
    asm volatile("mma.sync.aligned.m16n8k16.row.col.f32.bf16.bf16.f32 "
                 "{%0,%1,%2,%3}, {%4,%5,%6,%7}, {%8,%9}, {%0,%1,%2,%3};"
                 : "+f"(c[0]), "+f"(c[1]), "+f"(c[2]), "+f"(c[3])
                 : "r"(a[0]), "r"(a[1]), "r"(a[2]), "r"(a[3]), "r"(b[0]), "r"(b[1]));
}

__device__ __forceinline__ void split2(float x, bf16& h, bf16& l) {
    h = __float2bfloat16(x);
    l = __float2bfloat16(x - __bfloat162float(h));
}

// -------------------- conversion kernel --------------------
__global__ void conv_split_kernel(const float* __restrict__ src,
                                  bf16* __restrict__ dhi, bf16* __restrict__ dlo, int n) {
    int i = blockIdx.x * 256 + threadIdx.x;
    if (i < n) { bf16 h, l; split2(src[i], h, l); dhi[i] = h; dlo[i] = l; }
}

// -------------------- mask dtype sniffer --------------------
__global__ void detect_mask_kernel(const void* __restrict__ mask) {
    __shared__ int sF, sI;
    if (threadIdx.x == 0) { sF = 1; sI = 1; }
    __syncthreads();
    const float* mf = (const float*)mask;
    const int*   mi = (const int*)mask;
    int okF = 1, okI = 1;
    for (int i = threadIdx.x; i < 16384; i += 256) {
        float f = mf[i];
        okF &= ((f == 0.0f) | (f == 1.0f));
        int v = mi[i];
        okI &= ((v == 0) | (v == 1));
    }
    atomicAnd(&sF, okF);
    atomicAnd(&sI, okI);
    __syncthreads();
    if (threadIdx.x == 0) g_mask_mode = sF ? 0 : (sI ? 1 : 2);
}

// -------------------- tile loaders (cp.async) --------------------
// A tile: 128 rows x 32 cols bf16, smem row stride 80 B (64 data + 16 pad)
__device__ __forceinline__ void load_A(const bf16* __restrict__ A, uint32_t sA,
                                       int m0, int k0, int lda, int t) {
#pragma unroll
    for (int i = 0; i < 2; i++) {
        const int c = t + i * 256;
        const int row = c >> 2, j = c & 3;
        cpasync16(sA + row * 80 + j * 16, A + (long)(m0 + row) * lda + k0 + j * 8);
    }
}
// B TRANSB=true: [n][k] tile 128x32, same layout as A
__device__ __forceinline__ void load_Bt(const bf16* __restrict__ B, uint32_t sB,
                                        int n0, int k0, int ldb, int t) {
#pragma unroll
    for (int i = 0; i < 2; i++) {
        const int c = t + i * 256;
        const int row = c >> 2, j = c & 3;
        cpasync16(sB + row * 80 + j * 16, B + (long)(n0 + row) * ldb + k0 + j * 8);
    }
}
// B TRANSB=false: [k][n] tile 32x128, smem row stride 272 B (256 data + 16 pad)
__device__ __forceinline__ void load_Bn(const bf16* __restrict__ B, uint32_t sB,
                                        int n0, int k0, int ldb, int t) {
#pragma unroll
    for (int i = 0; i < 2; i++) {
        const int c = t + i * 256;
        const int row = c >> 4, j = c & 15;
        cpasync16(sB + row * 272 + j * 16, B + (long)(k0 + row) * ldb + n0 + j * 8);
    }
}

// -------------------- HMMA split-bf16 GEMM (128x128x32 tile, 8 warps) --------------------
// D[m,n] = sum_k A[m,k] * (TRANSB ? B[n,k] : B[k,n])
// 3 passes: Ahi*Bhi + Alo*Bhi + Ahi*Blo, fp32 register accumulation.
// EPI: 0 = fp32 C   1 = bf16 hi/lo (+optional bias)   3 = fp32 + bias + residual
template<int EPI, bool TRANSB>
__global__ void __launch_bounds__(256, 2) mma_gemm3(
    const bf16* __restrict__ Ahi, const bf16* __restrict__ Alo,
    const bf16* __restrict__ Bhi, const bf16* __restrict__ Blo,
    int K, int lda, int ldb,
    long aOffB, long aOffH, long bOffB, long bOffH, int Hdim,
    float* __restrict__ Cf, bf16* __restrict__ Chi, bf16* __restrict__ Clo,
    long cOffB, long cOffH, int ldc,
    const float* __restrict__ bias, const float* __restrict__ resid)
{
    extern __shared__ __align__(1024) char dynsmem[];
    const uint32_t sbase = smem_u32(dynsmem);

    const int t = threadIdx.x;
    const int lane = t & 31;
    const int wid = t >> 5;
    const int wm = wid >> 2;         // 0..1
    const int wn = wid & 3;          // 0..3

    const int z  = blockIdx.z;
    const int zb = z / Hdim, zh = z % Hdim;
    Ahi += (long)zb * aOffB + (long)zh * aOffH;
    Alo += (long)zb * aOffB + (long)zh * aOffH;
    Bhi += (long)zb * bOffB + (long)zh * bOffH;
    Blo += (long)zb * bOffB + (long)zh * bOffH;
    const long cOff = (long)zb * cOffB + (long)zh * cOffH;

    const int m0 = blockIdx.y * 128;
    const int n0 = blockIdx.x * 128;

    float acc[4][4][4];
#pragma unroll
    for (int i = 0; i < 4; i++)
#pragma unroll
        for (int j = 0; j < 4; j++)
#pragma unroll
            for (int r = 0; r < 4; r++) acc[i][j][r] = 0.0f;

    const int KC  = K >> 5;        // 32-wide chunks per pass
    const int NCH = 3 * KC;

    // prologue: chunk 0 (pass 0: hi*hi) into stage 0
    load_A(Ahi, sbase, m0, 0, lda, t);
    if (TRANSB) load_Bt(Bhi, sbase + 10240, n0, 0, ldb, t);
    else        load_Bn(Bhi, sbase + 10240, n0, 0, ldb, t);
    CP_COMMIT();

    // precomputed ldmatrix lane offsets
    const int arow = ((lane >> 3) & 1) * 8 + (lane & 7);
    const int akof = (lane >> 4) * 16;
    const int brow_t = ((lane >> 4) & 1) * 8 + (lane & 7);   // TRANSB=true
    const int bkof_t = ((lane >> 3) & 1) * 16;
    const int bkrow  = ((lane >> 3) & 1) * 8 + (lane & 7);   // TRANSB=false
    const int bnof   = ((lane >> 4) & 1) * 16;               // bytes

    for (int c = 0; c < NCH; c++) {
        if (c + 1 < NCH) {
            const int c2 = c + 1;
            const int p  = c2 / KC;
            const int k0 = (c2 - p * KC) << 5;
            const bf16* As = (p == 1) ? Alo : Ahi;
            const bf16* Bs = (p == 2) ? Blo : Bhi;
            const uint32_t st = sbase + (c2 & 1) * 20480;
            load_A(As, st, m0, k0, lda, t);
            if (TRANSB) load_Bt(Bs, st + 10240, n0, k0, ldb, t);
            else        load_Bn(Bs, st + 10240, n0, k0, ldb, t);
            CP_COMMIT();
            CP_WAIT1();
        } else {
            CP_WAIT0();
        }
        __syncthreads();

        const uint32_t sA = sbase + (c & 1) * 20480;
        const uint32_t sB = sA + 10240;
#pragma unroll
        for (int kk = 0; kk < 2; kk++) {
            uint32_t afr[4][4];
#pragma unroll
            for (int mt = 0; mt < 4; mt++)
                ldsm4(afr[mt], sA + (wm * 64 + mt * 16 + arow) * 80 + kk * 32 + akof);
            uint32_t bfr[2][4];
#pragma unroll
            for (int nt2 = 0; nt2 < 2; nt2++) {
                if (TRANSB)
                    ldsm4(bfr[nt2], sB + (wn * 32 + nt2 * 16 + brow_t) * 80 + kk * 32 + bkof_t);
                else
                    ldsm4t(bfr[nt2], sB + (kk * 16 + bkrow) * 272 + (wn * 32 + nt2 * 16) * 2 + bnof);
            }
#pragma unroll
            for (int mt = 0; mt < 4; mt++)
#pragma unroll
                for (int nt = 0; nt < 4; nt++)
                    mma16816(acc[mt][nt], afr[mt], &bfr[nt >> 1][(nt & 1) * 2]);
        }
        __syncthreads();
    }

    // ---------------- epilogue ----------------
    const int mbase = m0 + wm * 64 + (lane >> 2);
    const int nbase = n0 + wn * 32 + (lane & 3) * 2;
#pragma unroll
    for (int mt = 0; mt < 4; mt++) {
#pragma unroll
        for (int half = 0; half < 2; half++) {
            const int m = mbase + mt * 16 + half * 8;
#pragma unroll
            for (int nt = 0; nt < 4; nt++) {
                const int n = nbase + nt * 8;
                float v0 = acc[mt][nt][half * 2 + 0];
                float v1 = acc[mt][nt][half * 2 + 1];
                const long cb = cOff + (long)m * ldc + n;
                if (EPI == 0) {
                    *reinterpret_cast<float2*>(Cf + cb) = make_float2(v0, v1);
                } else if (EPI == 1) {
                    if (bias) { v0 += bias[n]; v1 += bias[n + 1]; }
                    bf16 h0, l0, h1, l1;
                    split2(v0, h0, l0); split2(v1, h1, l1);
                    *reinterpret_cast<__nv_bfloat162*>(Chi + cb) = __halves2bfloat162(h0, h1);
                    *reinterpret_cast<__nv_bfloat162*>(Clo + cb) = __halves2bfloat162(l0, l1);
                } else {  // EPI == 3
                    const float2 rv = *reinterpret_cast<const float2*>(resid + cb);
                    v0 += bias[n] + rv.x;
                    v1 += bias[n + 1] + rv.y;
                    *reinterpret_cast<float2*>(Cf + cb) = make_float2(v0, v1);
                }
            }
        }
    }
}

// -------------------- masked scaled softmax, writes bf16 hi/lo --------------------
__global__ void __launch_bounds__(256) softmax_kernel(const float* __restrict__ sc,
                                                      const void* __restrict__ mask,
                                                      bf16* __restrict__ at_hi,
                                                      bf16* __restrict__ at_lo)
{
    const long r = blockIdx.x;                // 0 .. B*H*S-1
    const int  i = (int)(r % Sv);
    const int  z = (int)(r / Sv);
    const int  b = z / Hv;
    const float* row = sc + r * (long)Sv;
    const long mbase = ((long)b * Sv + i) * (long)Sv;
    const int mode = g_mask_mode;
    const int t = threadIdx.x;

    float v[4];
#pragma unroll
    for (int u = 0; u < 4; u++) {
        const int j = u * 256 + t;
        float s = row[j] * 0.03125f;          // 1/sqrt(1024)
        bool m;
        if (mode == 0)      m = ((const float*)mask)[mbase + j] != 0.0f;
        else if (mode == 1) m = ((const int*)mask)[mbase + j] != 0;
        else                m = ((const unsigned char*)mask)[mbase + j] != 0;
        v[u] = m ? -1e9f : s;
    }

    __shared__ float red[8];
    const int lane = t & 31, warp = t >> 5;

    float mx = fmaxf(fmaxf(v[0], v[1]), fmaxf(v[2], v[3]));
#pragma unroll
    for (int o = 16; o > 0; o >>= 1) mx = fmaxf(mx, __shfl_xor_sync(0xffffffffu, mx, o));
    if (lane == 0) red[warp] = mx;
    __syncthreads();
    if (t < 32) {
        float m2 = (lane < 8) ? red[lane] : -3.4e38f;
#pragma unroll
        for (int o = 4; o > 0; o >>= 1) m2 = fmaxf(m2, __shfl_xor_sync(0xffffffffu, m2, o));
        if (lane == 0) red[0] = m2;
    }
    __syncthreads();
    mx = red[0];
    __syncthreads();

    float sum = 0.0f;
#pragma unroll
    for (int u = 0; u < 4; u++) { v[u] = expf(v[u] - mx); sum += v[u]; }
#pragma unroll
    for (int o = 16; o > 0; o >>= 1) sum += __shfl_xor_sync(0xffffffffu, sum, o);
    if (lane == 0) red[warp] = sum;
    __syncthreads();
    if (t < 32) {
        float s2 = (lane < 8) ? red[lane] : 0.0f;
#pragma unroll
        for (int o = 4; o > 0; o >>= 1) s2 += __shfl_xor_sync(0xffffffffu, s2, o);
        if (lane == 0) red[0] = s2;
    }
    __syncthreads();
    const float inv = 1.0f / red[0];

#pragma unroll
    for (int u = 0; u < 4; u++) {
        const long idx = r * (long)Sv + u * 256 + t;
        bf16 h, l;
        split2(v[u] * inv, h, l);
        at_hi[idx] = h;
        at_lo[idx] = l;
    }
}

// -------------------- LayerNorm over D=512 --------------------
__global__ void __launch_bounds__(128) ln_kernel(const float* __restrict__ x,
                                                 const float* __restrict__ gamma,
                                                 const float* __restrict__ beta,
                                                 float* __restrict__ out)
{
    const int r = blockIdx.x;
    const float* xr = x + (long)r * Dv;
    const int t = threadIdx.x;
    const int lane = t & 31, warp = t >> 5;
    __shared__ float red[4];

    float v[4];
    float s = 0.0f;
#pragma unroll
    for (int u = 0; u < 4; u++) { v[u] = xr[u * 128 + t]; s += v[u]; }
#pragma unroll
    for (int o = 16; o > 0; o >>= 1) s += __shfl_xor_sync(0xffffffffu, s, o);
    if (lane == 0) red[warp] = s;
    __syncthreads();
    if (t < 32) {
        float s2 = (lane < 4) ? red[lane] : 0.0f;
#pragma unroll
        for (int o = 2; o > 0; o >>= 1) s2 += __shfl_xor_sync(0xffffffffu, s2, o);
        if (lane == 0) red[0] = s2;
    }
    __syncthreads();
    const float mu = red[0] * (1.0f / Dv);
    __syncthreads();

    float sq = 0.0f;
#pragma unroll
    for (int u = 0; u < 4; u++) { float d = v[u] - mu; sq += d * d; }
#pragma unroll
    for (int o = 16; o > 0; o >>= 1) sq += __shfl_xor_sync(0xffffffffu, sq, o);
    if (lane == 0) red[warp] = sq;
    __syncthreads();
    if (t < 32) {
        float s2 = (lane < 4) ? red[lane] : 0.0f;
#pragma unroll
        for (int o = 2; o > 0; o >>= 1) s2 += __shfl_xor_sync(0xffffffffu, s2, o);
        if (lane == 0) red[0] = s2;
    }
    __syncthreads();
    const float inv = rsqrtf(red[0] * (1.0f / Dv) + 1e-5f);

    float* orow = out + (long)r * Dv;
#pragma unroll
    for (int u = 0; u < 4; u++) {
        const int c = u * 128 + t;
        orow[c] = (v[u] - mu) * inv * gamma[c] + beta[c];
    }
}

// -------------------- launch --------------------
extern "C" void kernel_launch(void* const* d_in, const int* in_sizes, int n_in,
                              void* d_out, int out_size)
{
    const float* Q    = (const float*)d_in[0];
    const float* K    = (const float*)d_in[1];
    const float* V    = (const float*)d_in[2];
    const void*  mask = (const void*) d_in[3];
    const float* Wq   = (const float*)d_in[4];
    const float* bq   = (const float*)d_in[5];
    const float* Wk   = (const float*)d_in[6];
    const float* bk   = (const float*)d_in[7];
    const float* Wv   = (const float*)d_in[8];
    const float* bv   = (const float*)d_in[9];
    const float* Wo   = (const float*)d_in[10];
    const float* bo   = (const float*)d_in[11];
    const float* gamma= (const float*)d_in[12];
    const float* beta = (const float*)d_in[13];
    float* out = (float*)d_out;

    void *p;
    bf16 *in_hi, *in_lo, *w_hi, *w_lo, *q_hi, *q_lo, *k_hi, *k_lo, *v_hi, *v_lo;
    bf16 *at_hi, *at_lo, *cx_hi, *cx_lo;
    float *sc, *res;
    cudaGetSymbolAddress(&p, g_in_hi); in_hi = (bf16*)p;
    cudaGetSymbolAddress(&p, g_in_lo); in_lo = (bf16*)p;
    cudaGetSymbolAddress(&p, g_w_hi);  w_hi  = (bf16*)p;
    cudaGetSymbolAddress(&p, g_w_lo);  w_lo  = (bf16*)p;
    cudaGetSymbolAddress(&p, g_q_hi);  q_hi  = (bf16*)p;
    cudaGetSymbolAddress(&p, g_q_lo);  q_lo  = (bf16*)p;
    cudaGetSymbolAddress(&p, g_k_hi);  k_hi  = (bf16*)p;
    cudaGetSymbolAddress(&p, g_k_lo);  k_lo  = (bf16*)p;
    cudaGetSymbolAddress(&p, g_v_hi);  v_hi  = (bf16*)p;
    cudaGetSymbolAddress(&p, g_v_lo);  v_lo  = (bf16*)p;
    cudaGetSymbolAddress(&p, g_at_hi); at_hi = (bf16*)p;
    cudaGetSymbolAddress(&p, g_at_lo); at_lo = (bf16*)p;
    cudaGetSymbolAddress(&p, g_cx_hi); cx_hi = (bf16*)p;
    cudaGetSymbolAddress(&p, g_cx_lo); cx_lo = (bf16*)p;
    cudaGetSymbolAddress(&p, g_sc);    sc    = (float*)p;
    cudaGetSymbolAddress(&p, g_res);   res   = (float*)p;

    const int SMEM = 40960;
    cudaFuncSetAttribute((const void*)mma_gemm3<0, true >, cudaFuncAttributeMaxDynamicSharedMemorySize, SMEM);
    cudaFuncSetAttribute((const void*)mma_gemm3<1, false>, cudaFuncAttributeMaxDynamicSharedMemorySize, SMEM);
    cudaFuncSetAttribute((const void*)mma_gemm3<3, false>, cudaFuncAttributeMaxDynamicSharedMemorySize, SMEM);

    detect_mask_kernel<<<1, 256>>>(mask);

    // split inputs + weights to bf16 hi/lo (natural layout, no transposes)
    const int NIN = Mrows * Dv;  // 4194304
    conv_split_kernel<<<NIN / 256, 256>>>(Q, in_hi, in_lo, NIN);
    conv_split_kernel<<<NIN / 256, 256>>>(K, in_hi + NIN, in_lo + NIN, NIN);
    conv_split_kernel<<<NIN / 256, 256>>>(V, in_hi + 2L * NIN, in_lo + 2L * NIN, NIN);
    conv_split_kernel<<<NIN / 256, 256>>>(Wq, w_hi, w_lo, NIN);
    conv_split_kernel<<<NIN / 256, 256>>>(Wk, w_hi + NIN, w_lo + NIN, NIN);
    conv_split_kernel<<<NIN / 256, 256>>>(Wv, w_hi + 2L * NIN, w_lo + 2L * NIN, NIN);
    conv_split_kernel<<<NIN / 256, 256>>>(Wo, w_hi + 3L * NIN, w_lo + 3L * NIN, NIN);

    // QKV projections: M=8192, N=8192, K=512; B = W [k][n]
    {
        dim3 grid(HDH / 128, Mrows / 128, 1);
        mma_gemm3<1, false><<<grid, 256, SMEM>>>(in_hi, in_lo, w_hi, w_lo,
            Dv, Dv, HDH, 0, 0, 0, 0, 1,
            nullptr, q_hi, q_lo, 0, 0, HDH, bq, nullptr);
        mma_gemm3<1, false><<<grid, 256, SMEM>>>(in_hi + NIN, in_lo + NIN, w_hi + NIN, w_lo + NIN,
            Dv, Dv, HDH, 0, 0, 0, 0, 1,
            nullptr, k_hi, k_lo, 0, 0, HDH, bk, nullptr);
        mma_gemm3<1, false><<<grid, 256, SMEM>>>(in_hi + 2L * NIN, in_lo + 2L * NIN,
            w_hi + 2L * NIN, w_lo + 2L * NIN,
            Dv, Dv, HDH, 0, 0, 0, 0, 1,
            nullptr, v_hi, v_lo, 0, 0, HDH, bv, nullptr);
    }

    // scores: per (b,h): q [S,DH] x k [S,DH]^T -> fp32 [S,S]
    {
        dim3 grid(Sv / 128, Sv / 128, Bv * Hv);
        mma_gemm3<0, true><<<grid, 256, SMEM>>>(q_hi, q_lo, k_hi, k_lo,
            DHv, HDH, HDH,
            (long)Sv * HDH, (long)DHv, (long)Sv * HDH, (long)DHv, Hv,
            sc, nullptr, nullptr, (long)Hv * Sv * Sv, (long)Sv * Sv, Sv,
            nullptr, nullptr);
    }

    // masked softmax -> bf16 hi/lo attn
    softmax_kernel<<<Bv * Hv * Sv, 256>>>(sc, mask, at_hi, at_lo);

    // ctx: per (b,h): attn [S,S] x v [S,DH] -> ctx [S,DH];  B = v [k][n]
    {
        dim3 grid(DHv / 128, Sv / 128, Bv * Hv);
        mma_gemm3<1, false><<<grid, 256, SMEM>>>(at_hi, at_lo, v_hi, v_lo,
            Sv, Sv, HDH,
            (long)Hv * Sv * Sv, (long)Sv * Sv, (long)Sv * HDH, (long)DHv, Hv,
            nullptr, cx_hi, cx_lo, (long)Sv * HDH, (long)DHv, HDH,
            nullptr, nullptr);
    }

    // out proj + bias + residual: M=8192, N=512, K=8192; B = Wo [k][n]
    {
        dim3 grid(Dv / 128, Mrows / 128, 1);
        mma_gemm3<3, false><<<grid, 256, SMEM>>>(cx_hi, cx_lo, w_hi + 3L * NIN, w_lo + 3L * NIN,
            HDH, HDH, Dv, 0, 0, 0, 0, 1,
            res, nullptr, nullptr, 0, 0, Dv, bo, Q);
    }

    // LayerNorm
    ln_kernel<<<Mrows, 128>>>(res, gamma, beta, out);
}